// round 8
// baseline (speedup 1.0000x reference)
#include <cuda_runtime.h>
#include <cstdint>

#define BB 4
#define SS 512
#define DD 128
#define HH 8
#define SC_PITCH 516

// scratch (static device memory; no runtime allocation)
__device__ float g_q[BB*SS*DD];
__device__ float g_k[BB*SS*DD];
__device__ float g_v[BB*SS*DD];
__device__ float g_attn[BB*SS*DD];
__device__ float g_bias[(size_t)BB*SS*SS*HH];   // [b*S+q][k][h], h innermost

// ---------------- f32x2 helpers ----------------
__device__ __forceinline__ unsigned long long pack2(float x) {
    unsigned long long r;
    asm("mov.b64 %0, {%1, %1};" : "=l"(r) : "f"(x));
    return r;
}
__device__ __forceinline__ unsigned long long pack2v(float lo, float hi) {
    unsigned long long r;
    asm("mov.b64 %0, {%1, %2};" : "=l"(r) : "f"(lo), "f"(hi));
    return r;
}
__device__ __forceinline__ void fma2(unsigned long long& d, unsigned long long a, unsigned long long b) {
    asm("fma.rn.f32x2 %0, %1, %2, %0;" : "+l"(d) : "l"(a), "l"(b));
}
__device__ __forceinline__ void mul2(unsigned long long& d, unsigned long long a, unsigned long long b) {
    asm("mul.rn.f32x2 %0, %1, %2;" : "=l"(d) : "l"(a), "l"(b));
}
__device__ __forceinline__ void add2(unsigned long long& d, unsigned long long a) {
    asm("add.rn.f32x2 %0, %1, %0;" : "+l"(d) : "l"(a));
}
__device__ __forceinline__ void unpack2(unsigned long long v, float& lo, float& hi) {
    asm("mov.b64 {%0, %1}, %2;" : "=f"(lo), "=f"(hi) : "l"(v));
}
__device__ __forceinline__ unsigned long long shfl_xor64(unsigned long long v, int m) {
    return __shfl_xor_sync(0xffffffffu, v, m);
}

// ---------------------------------------------------------------------------
// Kernel A: QKV projection, register-blocked outer product.
// grid = (128, 3) [by = matrix], block = 256 (8 warps).
// Warp = 16 output cols (c0 = wid*16) for all 16 rows; lane = (r=lane&15, ch=lane>>4).
// smem: ws[128][136] (69.6KB) + xs[16][129] (8.3KB)
// ---------------------------------------------------------------------------
__global__ __launch_bounds__(256) void qkv_kernel(
    const float* __restrict__ x,
    const float* __restrict__ wq, const float* __restrict__ bq,
    const float* __restrict__ wk, const float* __restrict__ bk,
    const float* __restrict__ wv, const float* __restrict__ bv)
{
    extern __shared__ float sm[];
    float* ws = sm;                    // [128][136]
    float* xs = sm + 128 * 136;        // [16][129]

    const int t = threadIdx.x;
    const int mat = blockIdx.y;
    const int row0 = blockIdx.x * 16;

    const float* W    = (mat == 0) ? wq : (mat == 1) ? wk : wv;
    const float* bias = (mat == 0) ? bq : (mat == 1) ? bk : bv;
    float* out        = (mat == 0) ? g_q : (mat == 1) ? g_k : g_v;

    // stage W (pitch 136) + x (pitch 129, scalar)
    #pragma unroll
    for (int i = t; i < 4096; i += 256) {
        int d = i >> 5, c4 = i & 31;
        *(float4*)(ws + d * 136 + c4 * 4) = ((const float4*)W)[i];
    }
    #pragma unroll
    for (int i = t; i < 2048; i += 256) {
        int r = i >> 7, c = i & 127;
        xs[r * 129 + c] = x[(size_t)(row0 + r) * DD + c];
    }
    __syncthreads();

    const int lane = t & 31;
    const int wid  = t >> 5;
    const int r  = lane & 15;
    const int ch = lane >> 4;
    const int c0 = wid * 16 + ch * 8;

    const float* xrow = xs + r * 129;
    const float* wbase = ws + c0;

    unsigned long long acc[4] = {0ull, 0ull, 0ull, 0ull};
    #pragma unroll 8
    for (int d = 0; d < 128; d++) {
        unsigned long long xp = pack2(xrow[d]);
        const ulonglong2* wrow = (const ulonglong2*)(wbase + d * 136);
        ulonglong2 w01 = wrow[0];
        ulonglong2 w23 = wrow[1];
        fma2(acc[0], xp, w01.x); fma2(acc[1], xp, w01.y);
        fma2(acc[2], xp, w23.x); fma2(acc[3], xp, w23.y);
    }
    float4 bb0 = *(const float4*)(bias + c0);
    float4 bb1 = *(const float4*)(bias + c0 + 4);
    float4 o0, o1;
    unpack2(acc[0], o0.x, o0.y); unpack2(acc[1], o0.z, o0.w);
    unpack2(acc[2], o1.x, o1.y); unpack2(acc[3], o1.z, o1.w);
    o0.x += bb0.x; o0.y += bb0.y; o0.z += bb0.z; o0.w += bb0.w;
    o1.x += bb1.x; o1.y += bb1.y; o1.z += bb1.z; o1.w += bb1.w;
    float* orow = out + (size_t)(row0 + r) * DD + c0;
    *(float4*)orow = o0;
    *(float4*)(orow + 4) = o1;
}

// ---------------------------------------------------------------------------
// Kernel B: st_bias stream, f32x2 head-pair packing + u64 butterfly.
// bias[row][h] = sum_d st[row][d] * wst[d][h]; lane owns d=4l..4l+3, all 8 heads
// packed as 4 u64 (head pairs). block=256, grid=296 (2 CTA/SM), no smem.
// ---------------------------------------------------------------------------
#define BIAS_GRID 296
__global__ __launch_bounds__(256, 2) void bias_kernel(
    const float* __restrict__ st, const float* __restrict__ wst)
{
    const int lane = threadIdx.x & 31;

    // wreg2[dd][hp] = (wst[4l+dd][2hp], wst[4l+dd][2hp+1])
    unsigned long long wreg2[4][4];
    #pragma unroll
    for (int dd = 0; dd < 4; dd++)
        #pragma unroll
        for (int hp = 0; hp < 4; hp++)
            wreg2[dd][hp] = pack2v(wst[(4 * lane + dd) * HH + 2 * hp],
                                   wst[(4 * lane + dd) * HH + 2 * hp + 1]);

    const float4* st4 = (const float4*)st;
    const unsigned gw = blockIdx.x * 8 + (threadIdx.x >> 5);
    const size_t step = (size_t)BIAS_GRID * 8 * 4;
    const size_t NR = (size_t)BB * SS * SS;   // 1,048,576 rows
    const bool wr = ((lane & 7) == 0);
    const int hoff = lane >> 2;               // 0,2,4,6 at lanes 0,8,16,24

    size_t row = (size_t)gw * 4;
    float4 E[4];
    if (row < NR) {
        #pragma unroll
        for (int u = 0; u < 4; u++)
            E[u] = __ldcs(&st4[(row + u) * 32 + lane]);
    }

    for (; row < NR; row += step) {
        const size_t nrow = (row + step < NR) ? (row + step) : row;
        float4 N[4];
        #pragma unroll
        for (int u = 0; u < 4; u++)
            N[u] = __ldcs(&st4[(nrow + u) * 32 + lane]);

        #pragma unroll
        for (int u = 0; u < 4; u++) {
            const float4 e = E[u];
            unsigned long long ex = pack2(e.x), ey = pack2(e.y);
            unsigned long long ez = pack2(e.z), ew = pack2(e.w);

            unsigned long long q0, q1, q2, q3;
            mul2(q0, ex, wreg2[0][0]); fma2(q0, ey, wreg2[1][0]);
            fma2(q0, ez, wreg2[2][0]); fma2(q0, ew, wreg2[3][0]);
            mul2(q1, ex, wreg2[0][1]); fma2(q1, ey, wreg2[1][1]);
            fma2(q1, ez, wreg2[2][1]); fma2(q1, ew, wreg2[3][1]);
            mul2(q2, ex, wreg2[0][2]); fma2(q2, ey, wreg2[1][2]);
            fma2(q2, ez, wreg2[2][2]); fma2(q2, ew, wreg2[3][2]);
            mul2(q3, ex, wreg2[0][3]); fma2(q3, ey, wreg2[1][3]);
            fma2(q3, ez, wreg2[2][3]); fma2(q3, ew, wreg2[3][3]);

            // stage mask16: low lanes keep (h0,h1),(h2,h3); hi keep (h4,h5),(h6,h7)
            const bool hi16 = (lane & 16);
            unsigned long long k0 = hi16 ? q2 : q0, g0 = hi16 ? q0 : q2;
            unsigned long long k1 = hi16 ? q3 : q1, g1 = hi16 ? q1 : q3;
            add2(k0, shfl_xor64(g0, 16));
            add2(k1, shfl_xor64(g1, 16));
            // stage mask8
            const bool m8 = (lane & 8);
            unsigned long long kk = m8 ? k1 : k0, gg = m8 ? k0 : k1;
            add2(kk, shfl_xor64(gg, 8));
            // plain allreduce over remaining lane bits
            add2(kk, shfl_xor64(kk, 4));
            add2(kk, shfl_xor64(kk, 2));
            add2(kk, shfl_xor64(kk, 1));

            if (wr) {
                float lo, hi;
                unpack2(kk, lo, hi);
                *(float2*)(g_bias + (row + u) * HH + hoff) = make_float2(lo, hi);
            }
        }
        #pragma unroll
        for (int u = 0; u < 4; u++) E[u] = N[u];
    }
}

// ---------------------------------------------------------------------------
// Kernel C: attention (qk + bias + mask + softmax + PV).
// grid = 256 (b = bx>>6, q0 = (bx&63)*8), block = 512, ~168KB dyn smem
// ---------------------------------------------------------------------------
__global__ __launch_bounds__(512, 1) void attn_kernel(const int* __restrict__ mask)
{
    extern __shared__ float smem[];
    float* scores = smem;                               // [8][8][SC_PITCH]
    float* qs     = scores + 8 * 8 * SC_PITCH;          // [8][128]
    float* mask_s = qs + 8 * 128;                       // [512]
    float* rinv_s = mask_s + 512;                       // [64] (q*8+h)
    float* ks     = rinv_s + 64;                        // [64][132]; reused as outp[2][8][8][16]

    const int tid  = threadIdx.x;
    const int lane = tid & 31;
    const int wid  = tid >> 5;
    const int b    = blockIdx.x >> 6;
    const int q0   = (blockIdx.x & 63) * 8;

    if (tid < 256)
        ((float4*)qs)[tid] = ((const float4*)(g_q + (size_t)(b * SS + q0) * DD))[tid];
    mask_s[tid] = mask[b * SS + tid] ? -10000.0f : 0.0f;
    __syncthreads();

    // ---------------- Phase 1: scores = qk/4 + bias ----------------
    {
        const int q  = tid >> 6;   // 0..7
        const int kl = tid & 63;   // 0..63
        for (int kc = 0; kc < 8; kc++) {
            const float4* kg = (const float4*)(g_k + (size_t)(b * SS + kc * 64) * DD);
            #pragma unroll
            for (int idx = tid; idx < 64 * 32; idx += 512)
                ((float4*)ks)[(idx >> 5) * 33 + (idx & 31)] = kg[idx];
            __syncthreads();

            unsigned long long acc2[8];
            #pragma unroll
            for (int h = 0; h < 8; h++) acc2[h] = 0ull;
            const ulonglong2* kr = (const ulonglong2*)(ks + kl * 132);
            const ulonglong2* qr = (const ulonglong2*)(qs + q * 128);
            #pragma unroll
            for (int j = 0; j < 32; j++) {
                ulonglong2 a = qr[j], c = kr[j];
                fma2(acc2[j >> 2], a.x, c.x);
                fma2(acc2[j >> 2], a.y, c.y);
            }
            const float4* brow = (const float4*)(g_bias +
                ((size_t)(b * SS + q0 + q) * SS + kc * 64 + kl) * HH);
            float4 b0 = __ldg(brow);
            float4 b1 = __ldg(brow + 1);
            float bh[8] = {b0.x, b0.y, b0.z, b0.w, b1.x, b1.y, b1.z, b1.w};

            float* sdst = scores + (q * 8) * SC_PITCH + kc * 64 + kl;
            #pragma unroll
            for (int h = 0; h < 8; h++) {
                float lo, hi;
                unpack2(acc2[h], lo, hi);
                sdst[h * SC_PITCH] = fmaf(lo + hi, 0.25f, bh[h]);
            }
            __syncthreads();
        }
    }

    // ---------------- Phase 2: softmax per (q,h) row ----------------
    for (int rr = wid; rr < 64; rr += 16) {
        float* srow = scores + rr * SC_PITCH;
        float vals[16];
        float mx = -1e30f;
        #pragma unroll
        for (int j = 0; j < 16; j++) {
            int k = lane + 32 * j;
            float v = srow[k] + mask_s[k];
            vals[j] = v;
            mx = fmaxf(mx, v);
        }
        #pragma unroll
        for (int o = 16; o > 0; o >>= 1) mx = fmaxf(mx, __shfl_xor_sync(0xffffffffu, mx, o));
        float sum = 0.f;
        #pragma unroll
        for (int j = 0; j < 16; j++) {
            float e = __expf(vals[j] - mx);
            srow[lane + 32 * j] = e;
            sum += e;
        }
        #pragma unroll
        for (int o = 16; o > 0; o >>= 1) sum += __shfl_xor_sync(0xffffffffu, sum, o);
        if (lane == 0) rinv_s[rr] = 1.0f / sum;
    }
    __syncthreads();

    // ---------------- Phase 3: PV (f32x2 over k-pairs, probs via LDS.128) ----
    float* outp = ks;   // reuse: [2][8][8][16]
    {
        const int h   = wid & 7;
        const int ks2 = wid >> 3;      // k-half
        const int e   = lane & 15;
        const int kk  = lane >> 4;     // 0/1
        const float* vbase = g_v + (size_t)(b * SS) * DD + h * 16 + e;
        const float* sbase = scores + h * SC_PITCH;

        unsigned long long acc2[8];
        #pragma unroll
        for (int q = 0; q < 8; q++) acc2[q] = 0ull;

        const int kstart = ks2 * 256 + kk * 4;
        #pragma unroll 4
        for (int i = 0; i < 32; i++) {
            const int k4 = kstart + i * 8;
            float v0 = vbase[(size_t)(k4 + 0) * DD];
            float v1 = vbase[(size_t)(k4 + 1) * DD];
            float v2 = vbase[(size_t)(k4 + 2) * DD];
            float v3 = vbase[(size_t)(k4 + 3) * DD];
            unsigned long long vp01 = pack2v(v0, v1);
            unsigned long long vp23 = pack2v(v2, v3);
            #pragma unroll
            for (int q = 0; q < 8; q++) {
                ulonglong2 p2 = *(const ulonglong2*)(sbase + q * 8 * SC_PITCH + k4);
                fma2(acc2[q], p2.x, vp01);
                fma2(acc2[q], p2.y, vp23);
            }
        }
        #pragma unroll
        for (int q = 0; q < 8; q++) {
            float lo, hi;
            unpack2(acc2[q], lo, hi);
            float s = lo + hi;
            s += __shfl_xor_sync(0xffffffffu, s, 16);
            if (lane < 16)
                outp[((ks2 * 8 + h) * 8 + q) * 16 + e] = s;
        }
    }
    __syncthreads();

    #pragma unroll
    for (int id = tid; id < 1024; id += 512) {
        int e = id & 15, q = (id >> 4) & 7, h = id >> 7;
        float val = (outp[((0 * 8 + h) * 8 + q) * 16 + e] +
                     outp[((1 * 8 + h) * 8 + q) * 16 + e]) * rinv_s[q * 8 + h];
        g_attn[(size_t)(b * SS + q0 + q) * DD + h * 16 + e] = val;
    }
}

// ---------------------------------------------------------------------------
// Kernel D: out = LN(residual + attn @ wo + bo), register-blocked outer product.
// grid = 128 (16 rows/block), block = 256 (8 warps).
// smem: ws[128][136] + as[16][129] + ys[16][132]
// ---------------------------------------------------------------------------
__global__ __launch_bounds__(256) void out_ln_kernel(
    const float* __restrict__ x, const float* __restrict__ wo,
    const float* __restrict__ bo, const float* __restrict__ g,
    const float* __restrict__ bbeta, float* __restrict__ out)
{
    extern __shared__ float sm[];
    float* ws = sm;                           // [128][136]
    float* as_ = sm + 128 * 136;              // [16][129]
    float* ys  = as_ + 16 * 129;              // [16][132]

    const int row0 = blockIdx.x * 16;
    const int t = threadIdx.x;

    #pragma unroll
    for (int i = t; i < 4096; i += 256) {
        int d = i >> 5, c4 = i & 31;
        *(float4*)(ws + d * 136 + c4 * 4) = ((const float4*)wo)[i];
    }
    #pragma unroll
    for (int i = t; i < 2048; i += 256) {
        int r = i >> 7, c = i & 127;
        as_[r * 129 + c] = g_attn[(size_t)(row0 + r) * DD + c];
    }
    __syncthreads();

    const int lane = t & 31;
    const int wid  = t >> 5;
    {
        const int r  = lane & 15;
        const int ch = lane >> 4;
        const int c0 = wid * 16 + ch * 8;

        const float* arow = as_ + r * 129;
        const float* wbase = ws + c0;

        unsigned long long acc[4] = {0ull, 0ull, 0ull, 0ull};
        #pragma unroll 8
        for (int d = 0; d < 128; d++) {
            unsigned long long xp = pack2(arow[d]);
            const ulonglong2* wrow = (const ulonglong2*)(wbase + d * 136);
            ulonglong2 w01 = wrow[0];
            ulonglong2 w23 = wrow[1];
            fma2(acc[0], xp, w01.x); fma2(acc[1], xp, w01.y);
            fma2(acc[2], xp, w23.x); fma2(acc[3], xp, w23.y);
        }
        float4 bb0 = *(const float4*)(bo + c0);
        float4 bb1 = *(const float4*)(bo + c0 + 4);
        const float* xrow = x + (size_t)(row0 + r) * DD + c0;
        float4 x0 = *(const float4*)xrow;
        float4 x1 = *(const float4*)(xrow + 4);
        float4 o0, o1;
        unpack2(acc[0], o0.x, o0.y); unpack2(acc[1], o0.z, o0.w);
        unpack2(acc[2], o1.x, o1.y); unpack2(acc[3], o1.z, o1.w);
        o0.x += bb0.x + x0.x; o0.y += bb0.y + x0.y;
        o0.z += bb0.z + x0.z; o0.w += bb0.w + x0.w;
        o1.x += bb1.x + x1.x; o1.y += bb1.y + x1.y;
        o1.z += bb1.z + x1.z; o1.w += bb1.w + x1.w;
        float* yrow = ys + r * 132 + c0;
        *(float4*)yrow = o0;
        *(float4*)(yrow + 4) = o1;
    }
    __syncthreads();

    // LayerNorm: 8 warps x 2 rows
    #pragma unroll
    for (int rr = 0; rr < 2; rr++) {
        const int row = wid * 2 + rr;
        float4 v = ((float4*)(ys + row * 132))[lane];
        float s = v.x + v.y + v.z + v.w;
        #pragma unroll
        for (int o = 16; o > 0; o >>= 1) s += __shfl_xor_sync(0xffffffffu, s, o);
        float mu = s * (1.f / 128.f);
        float dx = v.x - mu, dy = v.y - mu, dz = v.z - mu, dw = v.w - mu;
        float ss = dx * dx + dy * dy + dz * dz + dw * dw;
        #pragma unroll
        for (int o = 16; o > 0; o >>= 1) ss += __shfl_xor_sync(0xffffffffu, ss, o);
        float rstd = rsqrtf(ss * (1.f / 128.f) + 1e-5f);
        float4 gg = ((const float4*)g)[lane];
        float4 bb2 = ((const float4*)bbeta)[lane];
        float4 o4;
        o4.x = dx * rstd * gg.x + bb2.x;
        o4.y = dy * rstd * gg.y + bb2.y;
        o4.z = dz * rstd * gg.z + bb2.z;
        o4.w = dw * rstd * gg.w + bb2.w;
        ((float4*)(out + (size_t)(row0 + row) * DD))[lane] = o4;
    }
}

// ---------------------------------------------------------------------------
extern "C" void kernel_launch(void* const* d_in, const int* in_sizes, int n_in,
                              void* d_out, int out_size)
{
    const float* x    = (const float*)d_in[0];
    const float* st   = (const float*)d_in[1];
    const int*   mask = (const int*)  d_in[2];
    const float* wq   = (const float*)d_in[3];
    const float* bq   = (const float*)d_in[4];
    const float* wk   = (const float*)d_in[5];
    const float* bk   = (const float*)d_in[6];
    const float* wv   = (const float*)d_in[7];
    const float* bv   = (const float*)d_in[8];
    const float* wo   = (const float*)d_in[9];
    const float* bo   = (const float*)d_in[10];
    const float* wst  = (const float*)d_in[11];
    const float* lng  = (const float*)d_in[12];
    const float* lnb  = (const float*)d_in[13];
    float* out = (float*)d_out;

    const int SMEM_QKV  = (128 * 136 + 16 * 129) * 4;                              // 77888 B
    const int SMEM_ATTN = (8 * 8 * SC_PITCH + 8 * 128 + 512 + 64 + 64 * 132) * 4;  // 172288 B
    const int SMEM_OLN  = (128 * 136 + 16 * 129 + 16 * 132) * 4;                   // 86336 B
    cudaFuncSetAttribute(qkv_kernel,  cudaFuncAttributeMaxDynamicSharedMemorySize, SMEM_QKV);
    cudaFuncSetAttribute(attn_kernel, cudaFuncAttributeMaxDynamicSharedMemorySize, SMEM_ATTN);
    cudaFuncSetAttribute(out_ln_kernel, cudaFuncAttributeMaxDynamicSharedMemorySize, SMEM_OLN);

    bias_kernel<<<BIAS_GRID, 256>>>(st, wst);
    qkv_kernel<<<dim3(128, 3), 256, SMEM_QKV>>>(x, wq, bq, wk, bk, wv, bv);
    attn_kernel<<<256, 512, SMEM_ATTN>>>(mask);
    out_ln_kernel<<<128, 256, SMEM_OLN>>>(x, wo, bo, lng, lnb, out);
}